// round 13
// baseline (speedup 1.0000x reference)
#include <cuda_runtime.h>
#include <cuda_bf16.h>
#include <cstdint>
#include <cstddef>

typedef unsigned long long u64;
typedef __nv_bfloat16 bf16;

#define Bn 8
#define Cn 256
#define Nn 4096
#define SPLITS 4
#define CN ((size_t)Cn * Nn)
#define STG 32768  // bytes per pipeline stage (A 16K + B 16K)
#define RING 6

// ---------------- device scratch (no allocations allowed) ----------------
__device__ bf16 g_Xh[Bn * Cn * Nn], g_Xl[Bn * Cn * Nn];     // x hi/lo [b][c][n]
__device__ bf16 g_FGHh[Bn * 3 * Cn * Nn], g_FGHl[Bn * 3 * Cn * Nn];
__device__ bf16 g_Wsh[4 * Cn * Cn], g_Wsl[4 * Cn * Cn];     // stacked weights
__device__ bf16 g_Wph[Bn * Cn * Cn], g_Wpl[Bn * Cn * Cn];   // Wo' = Wo x beta
__device__ float g_bstk[3 * Cn];
__device__ float g_sPart[SPLITS * Bn * Cn * Cn];
__device__ bf16 g_betah[Bn * Cn * Cn], g_betal[Bn * Cn * Cn];

// ---------------- helpers -------------------------------------------------
#define SWZ(o) ((o) ^ (((o) >> 3) & 0x70))

__device__ __forceinline__ uint32_t s2u(const void* p) {
    uint32_t a;
    asm("{ .reg .u64 t; cvta.to.shared.u64 t, %1; cvt.u32.u64 %0, t; }"
        : "=r"(a) : "l"(p));
    return a;
}
__device__ __forceinline__ uint32_t splitpk_hi(float a, float b, uint32_t& lo) {
    bf16 h0 = __float2bfloat16(a), h1 = __float2bfloat16(b);
    bf16 l0 = __float2bfloat16(a - __bfloat162float(h0));
    bf16 l1 = __float2bfloat16(b - __bfloat162float(h1));
    lo = (uint32_t)__bfloat16_as_ushort(l0) |
         ((uint32_t)__bfloat16_as_ushort(l1) << 16);
    return (uint32_t)__bfloat16_as_ushort(h0) |
           ((uint32_t)__bfloat16_as_ushort(h1) << 16);
}
__device__ __forceinline__ void ldm4(uint32_t* r, uint32_t addr) {
    asm volatile(
        "ldmatrix.sync.aligned.m8n8.x4.shared.b16 {%0,%1,%2,%3}, [%4];"
        : "=r"(r[0]), "=r"(r[1]), "=r"(r[2]), "=r"(r[3]) : "r"(addr));
}
__device__ __forceinline__ void ldm4t(uint32_t* r, uint32_t addr) {
    asm volatile(
        "ldmatrix.sync.aligned.m8n8.x4.trans.shared.b16 {%0,%1,%2,%3}, [%4];"
        : "=r"(r[0]), "=r"(r[1]), "=r"(r[2]), "=r"(r[3]) : "r"(addr));
}
__device__ __forceinline__ void mma16816(float* c, const uint32_t* a,
                                         uint32_t b0, uint32_t b1) {
    asm volatile(
        "mma.sync.aligned.m16n8k16.row.col.f32.bf16.bf16.f32 "
        "{%0,%1,%2,%3}, {%4,%5,%6,%7}, {%8,%9}, {%0,%1,%2,%3};"
        : "+f"(c[0]), "+f"(c[1]), "+f"(c[2]), "+f"(c[3])
        : "r"(a[0]), "r"(a[1]), "r"(a[2]), "r"(a[3]), "r"(b0), "r"(b1));
}
__device__ __forceinline__ void cpa16(uint32_t dst, const void* src) {
    asm volatile("cp.async.cg.shared.global [%0], [%1], 16;"
                 :: "r"(dst), "l"(src) : "memory");
}

// ---------------- HMMA GEMM, all-bf16, 6-stage cp.async ring, BK=32 -------
// 512 threads, 1 CTA/SM; warp grid 4x4, warp tile 32x32.
// D[m0:128][n0:128] = sum_k A[m][k]*B[n][k]; hi/lo split, 3-mma emulation
template <bool AT, bool BT, bool OB16>
__global__ __launch_bounds__(512, 1)
void gemm_bf(const bf16* __restrict__ Ah, const bf16* __restrict__ Al,
             const bf16* __restrict__ Bh, const bf16* __restrict__ Bl,
             size_t sA, size_t sB, int K, int splits,
             size_t Abat, size_t Bbat, size_t Obat,
             const float* __restrict__ bias, void* Oh_, void* Ol_, size_t sO) {
    extern __shared__ __align__(128) char smem[];
    const int tid = threadIdx.x, lane = tid & 31, wid = tid >> 5;
    const int wm = wid >> 2, wn = wid & 3;  // 4x4 warp grid, 32x32 tiles
    const int z = blockIdx.z, b = z / splits, sp = z - b * splits;
    const int kb = sp * K;
    const int m0 = blockIdx.y * 128, n0 = blockIdx.x * 128;
    const uint32_t sb = s2u(smem);

    const bf16* A0 = AT ? (Ah + Abat * b + (size_t)kb * sA + m0)
                        : (Ah + Abat * b + (size_t)m0 * sA + kb);
    const bf16* A1 = AT ? (Al + Abat * b + (size_t)kb * sA + m0)
                        : (Al + Abat * b + (size_t)m0 * sA + kb);
    const bf16* B0 = BT ? (Bh + Bbat * b + (size_t)kb * sB + n0)
                        : (Bh + Bbat * b + (size_t)n0 * sB + kb);
    const bf16* B1 = BT ? (Bl + Bbat * b + (size_t)kb * sB + n0)
                        : (Bl + Bbat * b + (size_t)n0 * sB + kb);

    // per-stage operand region: 1024 chunks of 16B (hi 8K + lo 8K)
#define LOAD_OP(TR, off, Phi, Plo, stride, s)                                 \
    if constexpr (TR) {                                                       \
        _Pragma("unroll") for (int i = 0; i < 2; ++i) {                       \
            int ch = tid + 512 * i;                                           \
            int kr = ch >> 5, rest = ch & 31;                                 \
            int hl = rest >> 4, cq = rest & 15;                               \
            uint32_t o = hl * 8192 + (cq >> 3) * 4096 +                       \
                         SWZ(kr * 128 + (cq & 7) * 16);                       \
            const bf16* src = (hl ? (Plo) : (Phi)) +                          \
                              (size_t)((s) * 32 + kr) * (stride) + cq * 8;    \
            cpa16(bb + (off) + o, src);                                       \
        }                                                                     \
    } else {                                                                  \
        _Pragma("unroll") for (int i = 0; i < 2; ++i) {                       \
            int ch = tid + 512 * i;                                           \
            int r = ch >> 3, hl = (ch >> 2) & 1, q = ch & 3;                  \
            uint32_t o = SWZ(r * 128 + hl * 64 + q * 16);                     \
            const bf16* src = (hl ? (Plo) : (Phi)) +                          \
                              (size_t)r * (stride) + (s) * 32 + q * 8;        \
            cpa16(bb + (off) + o, src);                                       \
        }                                                                     \
    }

#define LOAD_SLAB(s, stg)                                                     \
    {                                                                         \
        const uint32_t bb = sb + (stg) * STG;                                 \
        LOAD_OP(AT, 0, A0, A1, sA, s);                                        \
        LOAD_OP(BT, 16384, B0, B1, sB, s);                                    \
        asm volatile("cp.async.commit_group;" ::: "memory");                  \
    }

    float acc[2][4][4] = {};
    const int NS = K / 32;
#pragma unroll
    for (int p = 0; p < RING - 1; ++p) LOAD_SLAB(p, p);

    for (int s = 0; s < NS; ++s) {
        const int stg = s % RING;
        asm volatile("cp.async.wait_group %0;" :: "n"(RING - 2) : "memory");
        __syncthreads();
        if (s + RING - 1 < NS) {
            LOAD_SLAB(s + RING - 1, (s + RING - 1) % RING);
        } else {
            asm volatile("cp.async.commit_group;" ::: "memory");  // empty
        }

        const uint32_t base = sb + stg * STG;
        const int trow = lane & 7, tsel = lane >> 3;
#pragma unroll
        for (int kk = 0; kk < 2; ++kk) {
            uint32_t aH[2][4], aL[2][4];
#pragma unroll
            for (int mt = 0; mt < 2; ++mt) {
                if constexpr (AT) {
                    int krow = kk * 16 + (tsel >> 1) * 8 + trow;
                    int mcol = wm * 32 + mt * 16 + (tsel & 1) * 8;
                    uint32_t o = (mcol >> 6) * 4096 +
                                 SWZ(krow * 128 + (mcol & 63) * 2);
                    ldm4t(aH[mt], base + o);
                    ldm4t(aL[mt], base + 8192 + o);
                } else {
                    int mr = wm * 32 + mt * 16 + (tsel & 1) * 8 + trow;
                    int kby = kk * 32 + (tsel >> 1) * 16;
                    ldm4(aH[mt], base + SWZ(mr * 128 + kby));
                    ldm4(aL[mt], base + SWZ(mr * 128 + 64 + kby));
                }
            }
#pragma unroll
            for (int np = 0; np < 2; ++np) {
                uint32_t bH[4], bL[4];
                if constexpr (BT) {
                    int krow = kk * 16 + (tsel & 1) * 8 + trow;
                    int ncol = wn * 32 + np * 16 + (tsel >> 1) * 8;
                    uint32_t o = (ncol >> 6) * 4096 +
                                 SWZ(krow * 128 + (ncol & 63) * 2);
                    ldm4t(bH, base + 16384 + o);
                    ldm4t(bL, base + 16384 + 8192 + o);
                } else {
                    int nr = wn * 32 + np * 16 + (tsel >> 1) * 8 + trow;
                    int kby = kk * 32 + (tsel & 1) * 16;
                    ldm4(bH, base + 16384 + SWZ(nr * 128 + kby));
                    ldm4(bL, base + 16384 + SWZ(nr * 128 + 64 + kby));
                }
                // term-major ordering
#pragma unroll
                for (int mt = 0; mt < 2; ++mt)
#pragma unroll
                    for (int j = 0; j < 2; ++j)
                        mma16816(acc[mt][np * 2 + j], aH[mt], bH[2 * j],
                                 bH[2 * j + 1]);
#pragma unroll
                for (int mt = 0; mt < 2; ++mt)
#pragma unroll
                    for (int j = 0; j < 2; ++j)
                        mma16816(acc[mt][np * 2 + j], aH[mt], bL[2 * j],
                                 bL[2 * j + 1]);
#pragma unroll
                for (int mt = 0; mt < 2; ++mt)
#pragma unroll
                    for (int j = 0; j < 2; ++j)
                        mma16816(acc[mt][np * 2 + j], aL[mt], bH[2 * j],
                                 bH[2 * j + 1]);
            }
        }
    }

    // ---- epilogue
#pragma unroll
    for (int mt = 0; mt < 2; ++mt) {
        const int r0 = m0 + wm * 32 + mt * 16 + (lane >> 2);
        const float bz0 = bias ? bias[r0] : 0.f;
        const float bz1 = bias ? bias[r0 + 8] : 0.f;
#pragma unroll
        for (int nt = 0; nt < 4; ++nt) {
            const int col = n0 + wn * 32 + nt * 8 + 2 * (lane & 3);
            const float* c = acc[mt][nt];
            if constexpr (OB16) {
                bf16* oh = (bf16*)Oh_ + Obat * z;
                bf16* ol = (bf16*)Ol_ + Obat * z;
                uint32_t lo0, lo1;
                uint32_t hi0 = splitpk_hi(c[0] + bz0, c[1] + bz0, lo0);
                uint32_t hi1 = splitpk_hi(c[2] + bz1, c[3] + bz1, lo1);
                *(uint32_t*)(oh + (size_t)r0 * sO + col) = hi0;
                *(uint32_t*)(ol + (size_t)r0 * sO + col) = lo0;
                *(uint32_t*)(oh + (size_t)(r0 + 8) * sO + col) = hi1;
                *(uint32_t*)(ol + (size_t)(r0 + 8) * sO + col) = lo1;
            } else {
                float* o = (float*)Oh_ + Obat * z;
                *(float2*)(o + (size_t)r0 * sO + col) =
                    make_float2(c[0] + bz0, c[1] + bz0);
                *(float2*)(o + (size_t)(r0 + 8) * sO + col) =
                    make_float2(c[2] + bz1, c[3] + bz1);
            }
        }
    }
}

// ---------------- prep: split 4 weight matrices + stack biases ------------
__global__ __launch_bounds__(256) void prep_weights(
    const float* __restrict__ Wf, const float* __restrict__ Wg,
    const float* __restrict__ Wh, const float* __restrict__ Wo,
    const float* __restrict__ b0, const float* __restrict__ b1,
    const float* __restrict__ b2) {
    int idx = blockIdx.x * 256 + threadIdx.x;  // pair index, 4*32768 total
    const float* W = (idx >> 15) == 0 ? Wf
                     : (idx >> 15) == 1 ? Wg
                     : (idx >> 15) == 2 ? Wh : Wo;
    int p = idx & 32767;
    uint32_t lo, hi = splitpk_hi(W[2 * p], W[2 * p + 1], lo);
    ((uint32_t*)g_Wsh)[idx] = hi;
    ((uint32_t*)g_Wsl)[idx] = lo;
    if (blockIdx.x == 0) {
        g_bstk[threadIdx.x] = b0[threadIdx.x];
        g_bstk[256 + threadIdx.x] = b1[threadIdx.x];
        g_bstk[512 + threadIdx.x] = b2[threadIdx.x];
    }
}

// ---------------- streaming fp32 -> bf16 hi/lo split of x ------------------
__global__ __launch_bounds__(256) void convert_x(const float* __restrict__ x,
                                                 bf16* __restrict__ xh,
                                                 bf16* __restrict__ xl) {
    const size_t i8 = ((size_t)blockIdx.x * 256 + threadIdx.x) * 8;
    float4 v0 = *(const float4*)(x + i8);
    float4 v1 = *(const float4*)(x + i8 + 4);
    uint32_t hw[4], lw[4];
    hw[0] = splitpk_hi(v0.x, v0.y, lw[0]);
    hw[1] = splitpk_hi(v0.z, v0.w, lw[1]);
    hw[2] = splitpk_hi(v1.x, v1.y, lw[2]);
    hw[3] = splitpk_hi(v1.z, v1.w, lw[3]);
    *(uint4*)(xh + i8) = make_uint4(hw[0], hw[1], hw[2], hw[3]);
    *(uint4*)(xl + i8) = make_uint4(lw[0], lw[1], lw[2], lw[3]);
}

// ---------------- softmax over split-K partials -> bf16 hi/lo beta --------
__global__ __launch_bounds__(256) void softmax_kernel() {
    const int row = blockIdx.x;  // b*Cn + i
    const int b = row >> 8, i = row & 255;
    const int j = threadIdx.x;
    float v = 0.f;
#pragma unroll
    for (int sp = 0; sp < SPLITS; ++sp)
        v += g_sPart[((size_t)(b * SPLITS + sp) << 16) + i * Cn + j];
    __shared__ float red[256];
    red[j] = v;
    __syncthreads();
    for (int s = 128; s > 0; s >>= 1) {
        if (j < s) red[j] = fmaxf(red[j], red[j + s]);
        __syncthreads();
    }
    const float mx = red[0];
    __syncthreads();
    const float e = expf(v - mx);
    red[j] = e;
    __syncthreads();
    for (int s = 128; s > 0; s >>= 1) {
        if (j < s) red[j] += red[j + s];
        __syncthreads();
    }
    const float r = e / red[0];
    bf16 h = __float2bfloat16(r);
    bf16 l = __float2bfloat16(r - __bfloat162float(h));
    g_betah[(size_t)row * Cn + j] = h;
    g_betal[(size_t)row * Cn + j] = l;
}

// -------------------------------------------------------------------------
extern "C" void kernel_launch(void* const* d_in, const int* in_sizes, int n_in,
                              void* d_out, int out_size) {
    const float* x = (const float*)d_in[0];
    const float* Wf = (const float*)d_in[1];
    const float* bfp = (const float*)d_in[2];
    const float* Wg = (const float*)d_in[3];
    const float* bg = (const float*)d_in[4];
    const float* Wh = (const float*)d_in[5];
    const float* bh = (const float*)d_in[6];
    const float* Wo = (const float*)d_in[7];
    const float* bo = (const float*)d_in[8];
    float* out = (float*)d_out;

    bf16 *Xh, *Xl, *FGHh, *FGHl, *Wsh, *Wsl, *Wph, *Wpl, *betah, *betal;
    float *sPart, *bstk;
    cudaGetSymbolAddress((void**)&Xh, g_Xh);
    cudaGetSymbolAddress((void**)&Xl, g_Xl);
    cudaGetSymbolAddress((void**)&FGHh, g_FGHh);
    cudaGetSymbolAddress((void**)&FGHl, g_FGHl);
    cudaGetSymbolAddress((void**)&Wsh, g_Wsh);
    cudaGetSymbolAddress((void**)&Wsl, g_Wsl);
    cudaGetSymbolAddress((void**)&Wph, g_Wph);
    cudaGetSymbolAddress((void**)&Wpl, g_Wpl);
    cudaGetSymbolAddress((void**)&betah, g_betah);
    cudaGetSymbolAddress((void**)&betal, g_betal);
    cudaGetSymbolAddress((void**)&sPart, g_sPart);
    cudaGetSymbolAddress((void**)&bstk, g_bstk);

    const int SMSZ = RING * STG;  // 196608
    cudaFuncSetAttribute(gemm_bf<false, true, true>,
                         cudaFuncAttributeMaxDynamicSharedMemorySize, SMSZ);
    cudaFuncSetAttribute(gemm_bf<true, true, false>,
                         cudaFuncAttributeMaxDynamicSharedMemorySize, SMSZ);
    cudaFuncSetAttribute(gemm_bf<false, false, false>,
                         cudaFuncAttributeMaxDynamicSharedMemorySize, SMSZ);

    const size_t CC = (size_t)Cn * Cn;

    // 0) weights -> bf16 hi/lo (stacked), biases -> stacked
    prep_weights<<<512, 256>>>(Wf, Wg, Wh, Wo, bfp, bg, bh);

    // 1) x -> hi/lo (same [c][n] layout, no transpose)
    convert_x<<<(Bn * Cn * Nn) / (256 * 8), 256>>>(x, Xh, Xl);

    // 2) merged conv F,G,H: D[m][n] = sum_k Wstk[m][k] x[k][n]; B trans-mode
    gemm_bf<false, true, true><<<dim3(Nn / 128, 6, Bn), 512, SMSZ>>>(
        Wsh, Wsl, Xh, Xl, Cn, Nn, Cn, 1, 0, CN, 3 * CN, bstk, FGHh, FGHl, Nn);

    // 3) s partials: D[i][j] = sum_n Gr[n][i] Fr[n][j]; both trans-mode
    gemm_bf<true, true, false><<<dim3(2, 2, Bn * SPLITS), 512, SMSZ>>>(
        FGHh + CN, FGHl + CN, FGHh, FGHl, Cn, Cn, Nn / SPLITS, SPLITS,
        3 * CN, 3 * CN, CC, nullptr, sPart, nullptr, Cn);

    // 4) softmax -> beta bf16 hi/lo
    softmax_kernel<<<Bn * Cn, 256>>>();

    // 5) Wo' [o][j] = sum_i Wo[o][i] beta[i][j]  (beta as BT operand)
    gemm_bf<false, true, true><<<dim3(2, 2, Bn), 512, SMSZ>>>(
        Wsh + 3 * CC, Wsl + 3 * CC, betah, betal, Cn, Cn, Cn, 1,
        0, CC, CC, nullptr, Wph, Wpl, Cn);

    // 6) final: y[o][p] = sum_j Wo'[o][j] Hr[p][j] -> d_out fp32 [o][p]
    gemm_bf<false, false, false><<<dim3(Nn / 128, Cn / 128, Bn), 512, SMSZ>>>(
        Wph, Wpl, FGHh + 2 * CN, FGHl + 2 * CN, Cn, Cn, Cn, 1,
        CC, 3 * CN, CN, bo, out, nullptr, Nn);
}